// round 14
// baseline (speedup 1.0000x reference)
#include <cuda_runtime.h>
#include <cstdint>

#define CAND 512           // candidate buffer entries (u64)
#define TBL  1024          // bins per table
#define XSCALE 51.2f       // TBL / 20  (range [-10, 10])
#define XOFF   512.0f      // 10 * XSCALE
#define THRESH0 2.7f       // prefilter threshold (fallback makes any value correct)
#define FULLM 0xFFFFFFFFu
#define MROWS 4096
#define MSTR  1312         // mask bytes per row (supports C <= 10496)

static __device__ float g_rowsum[8192];
static __device__ float g_table[2 * TBL];          // [0..TBL)=f_neg, [TBL..2TBL)=f_pos
static __device__ unsigned char g_catbit[16384];   // (1<<(cat-1))&7
static __device__ unsigned char g_mask[MROWS * MSTR];  // nibble per quad, 2 quads/byte
static __device__ int   g_flagrow[MROWS];
static __device__ int   g_count = 0;

// ---------------------------------------------------------------------------
__device__ __forceinline__ unsigned sortkey32(float x) {
    unsigned u = __float_as_uint(x);
    return u ^ ((unsigned)(((int)u) >> 31) | 0x80000000u);
}
__device__ __forceinline__ unsigned long long makekey(unsigned k32, int c) {
    return ((unsigned long long)k32 << 32) |
           (unsigned long long)(0xFFFFFFFFu - (unsigned)c);
}
__device__ __forceinline__ int tbl_idx(float xv) {
    unsigned j = __float2uint_rz(fmaf(xv, XSCALE, XOFF));
    return (int)umin(j, (unsigned)(TBL - 1));
}

// ---------------------------------------------------------------------------
// Kernel 0: build loss tables (exact math) + catbit LUT + zero row flags.
// ---------------------------------------------------------------------------
__global__ void asl_build(const int* __restrict__ cat, int C)
{
    int j = blockIdx.x * 256 + threadIdx.x;
    if (j < 2 * TBL) {
        bool pos = j >= TBL;
        int  q   = pos ? j - TBL : j;
        float x  = (q + 0.5f) * (20.0f / TBL) - 10.0f;
        float sp = 1.0f / (1.0f + expf(-x));
        float v;
        if (pos) {
            v = logf(fmaxf(sp, 1e-8f)) * (1.0f - sp);
        } else {
            float pv = fminf(1.05f - sp, 1.0f);
            float om = 1.0f - pv;
            float om2 = om * om;
            v = logf(fmaxf(pv, 1e-8f)) * om2 * om2;
        }
        g_table[j] = v;
    }
    if (j < MROWS) g_flagrow[j] = 0;
    int c = j - 2 * TBL;
    if (c >= 0 && c < C)
        g_catbit[c] = (unsigned char)((1 << (cat[c] - 1)) & 7);
}

// ---------------------------------------------------------------------------
// Kernel 1: y-scan. One block per row: positive nibble mask + whitelist flags.
// ---------------------------------------------------------------------------
__global__ void __launch_bounds__(256, 8)
asl_ykernel(const float* __restrict__ Y, int C)
{
    const int row = blockIdx.x;
    const int tid = threadIdx.x;

    const size_t base = (size_t)row * (size_t)C;
    const float* __restrict__ yr = Y + base;
    const int p   = (int)((4 - (base & 3)) & 3);
    const int nvq = (C - p) >> 2;
    const float4* __restrict__ y4 = (const float4*)(yr + p);
    unsigned char* __restrict__ mrow = g_mask + (size_t)row * MSTR;

    int flags = 0;

    for (int v = tid; v < nvq; v += 256) {
        const float4 yq = __ldcs(y4 + v);
        unsigned n = (yq.x != 0.0f ? 1u : 0u) |
                     (yq.y != 0.0f ? 2u : 0u) |
                     (yq.z != 0.0f ? 4u : 0u) |
                     (yq.w != 0.0f ? 8u : 0u);
        unsigned hi = __shfl_down_sync(FULLM, n, 1);   // odd lane's nibble
        if ((tid & 1) == 0) {
            if (v + 1 >= nvq) hi = 0;
            mrow[v >> 1] = (unsigned char)(n | (hi << 4));
        }
        if (n) {
            const int c0 = p + (v << 2);
            if (n & 1) flags |= g_catbit[c0 + 0];
            if (n & 2) flags |= g_catbit[c0 + 1];
            if (n & 4) flags |= g_catbit[c0 + 2];
            if (n & 8) flags |= g_catbit[c0 + 3];
        }
    }
    // prologue + tail elements (not covered by quads)
    const int t0 = p + (nvq << 2);
    for (int c = tid; c < p; c += 256)
        if (yr[c] != 0.0f) flags |= g_catbit[c];
    for (int c = t0 + tid; c < C; c += 256)
        if (yr[c] != 0.0f) flags |= g_catbit[c];

#pragma unroll
    for (int off = 16; off; off >>= 1)
        flags |= __shfl_down_sync(FULLM, flags, off);
    if ((tid & 31) == 0 && flags) atomicOr(&g_flagrow[row], flags);
}

// ---------------------------------------------------------------------------
// Kernel 2: x-stream. 2 rows per block; 8 elements/iteration; mask byte for y.
// ---------------------------------------------------------------------------
__global__ void __launch_bounds__(256, 8)
asl_row_kernel(const float* __restrict__ X,
               const float* __restrict__ Y,
               const int*   __restrict__ cat,
               const unsigned char* __restrict__ inmap,
               int C, int B, float* __restrict__ out)
{
    const int tid  = threadIdx.x;
    const int lane = tid & 31;
    const int warp = tid >> 5;

    __shared__ float s_tbl[2 * TBL];              // 8 KB
    __shared__ unsigned long long s_buf[CAND];    // 4 KB
    __shared__ unsigned long long s_top[10];
    __shared__ float s_sumw[8];
    __shared__ int s_cnt, s_last;

    {   // table L2 -> smem
        const float4* gt = (const float4*)g_table;
        float4* st = (float4*)s_tbl;
#pragma unroll
        for (int i = tid; i < (2 * TBL) / 4; i += 256) st[i] = gt[i];
    }
    __syncthreads();

    for (int row = blockIdx.x; row < B; row += gridDim.x) {
        if (tid == 0) s_cnt = 0;
        __syncthreads();

        const size_t base = (size_t)row * (size_t)C;
        const float* __restrict__ xr = X + base;
        const float* __restrict__ yr = Y + base;
        const unsigned char* __restrict__ mrow = g_mask + (size_t)row * MSTR;

        float sum0 = 0.0f, sum1 = 0.0f;

        const int p  = (int)((4 - (base & 3)) & 3);
        const int n8 = (C - p) >> 3;          // full 8-element groups
        const int t0 = p + (n8 << 3);

        // prologue + tail: direct x/y scalar (flags handled by y-kernel)
        for (int c = tid; c < p; c += 256) {
            const float xv = xr[c];
            const int j = tbl_idx(xv);
            sum0 += s_tbl[j];
            if (yr[c] != 0.0f) sum0 += s_tbl[j + TBL] - s_tbl[j];
            if (xv > THRESH0) {
                int q = atomicAdd(&s_cnt, 1);
                if (q < CAND) s_buf[q] = makekey(sortkey32(xv), c);
            }
        }
        for (int c = t0 + tid; c < C; c += 256) {
            const float xv = xr[c];
            const int j = tbl_idx(xv);
            sum0 += s_tbl[j];
            if (yr[c] != 0.0f) sum0 += s_tbl[j + TBL] - s_tbl[j];
            if (xv > THRESH0) {
                int q = atomicAdd(&s_cnt, 1);
                if (q < CAND) s_buf[q] = makekey(sortkey32(xv), c);
            }
        }

        // ---- main loop: 8 consecutive elements, 2 LDG.128 + 1 LDG.U8 ----
        const float4* __restrict__ x8 = (const float4*)(xr + p);
        for (int v = tid; v < n8; v += 256) {
            const float4 xa = __ldcs(x8 + 2 * v);
            const float4 xb = __ldcs(x8 + 2 * v + 1);
            const unsigned m = mrow[v];

            sum0 += s_tbl[tbl_idx(xa.x)];
            sum1 += s_tbl[tbl_idx(xa.y)];
            sum0 += s_tbl[tbl_idx(xa.z)];
            sum1 += s_tbl[tbl_idx(xa.w)];
            sum0 += s_tbl[tbl_idx(xb.x)];
            sum1 += s_tbl[tbl_idx(xb.y)];
            sum0 += s_tbl[tbl_idx(xb.z)];
            sum1 += s_tbl[tbl_idx(xb.w)];

            const float xm = fmaxf(fmaxf(fmaxf(xa.x, xa.y), fmaxf(xa.z, xa.w)),
                                   fmaxf(fmaxf(xb.x, xb.y), fmaxf(xb.z, xb.w)));
            if ((xm > THRESH0) || (m != 0u)) {
                const int c0 = p + (v << 3);
                if (xm > THRESH0) {
                    if (xa.x > THRESH0) { int q = atomicAdd(&s_cnt, 1); if (q < CAND) s_buf[q] = makekey(sortkey32(xa.x), c0 + 0); }
                    if (xa.y > THRESH0) { int q = atomicAdd(&s_cnt, 1); if (q < CAND) s_buf[q] = makekey(sortkey32(xa.y), c0 + 1); }
                    if (xa.z > THRESH0) { int q = atomicAdd(&s_cnt, 1); if (q < CAND) s_buf[q] = makekey(sortkey32(xa.z), c0 + 2); }
                    if (xa.w > THRESH0) { int q = atomicAdd(&s_cnt, 1); if (q < CAND) s_buf[q] = makekey(sortkey32(xa.w), c0 + 3); }
                    if (xb.x > THRESH0) { int q = atomicAdd(&s_cnt, 1); if (q < CAND) s_buf[q] = makekey(sortkey32(xb.x), c0 + 4); }
                    if (xb.y > THRESH0) { int q = atomicAdd(&s_cnt, 1); if (q < CAND) s_buf[q] = makekey(sortkey32(xb.y), c0 + 5); }
                    if (xb.z > THRESH0) { int q = atomicAdd(&s_cnt, 1); if (q < CAND) s_buf[q] = makekey(sortkey32(xb.z), c0 + 6); }
                    if (xb.w > THRESH0) { int q = atomicAdd(&s_cnt, 1); if (q < CAND) s_buf[q] = makekey(sortkey32(xb.w), c0 + 7); }
                }
                if (m != 0u) {   // recompute j in the rare branch (no reg retention)
                    if (m & 0x01u) { int j = tbl_idx(xa.x); sum0 += s_tbl[j + TBL] - s_tbl[j]; }
                    if (m & 0x02u) { int j = tbl_idx(xa.y); sum1 += s_tbl[j + TBL] - s_tbl[j]; }
                    if (m & 0x04u) { int j = tbl_idx(xa.z); sum0 += s_tbl[j + TBL] - s_tbl[j]; }
                    if (m & 0x08u) { int j = tbl_idx(xa.w); sum1 += s_tbl[j + TBL] - s_tbl[j]; }
                    if (m & 0x10u) { int j = tbl_idx(xb.x); sum0 += s_tbl[j + TBL] - s_tbl[j]; }
                    if (m & 0x20u) { int j = tbl_idx(xb.y); sum1 += s_tbl[j + TBL] - s_tbl[j]; }
                    if (m & 0x40u) { int j = tbl_idx(xb.z); sum0 += s_tbl[j + TBL] - s_tbl[j]; }
                    if (m & 0x80u) { int j = tbl_idx(xb.w); sum1 += s_tbl[j + TBL] - s_tbl[j]; }
                }
            }
        }

        // ---- reduce sum ----
        float sum = sum0 + sum1;
#pragma unroll
        for (int off = 16; off; off >>= 1)
            sum += __shfl_down_sync(FULLM, sum, off);
        if (lane == 0) s_sumw[warp] = sum;
        __syncthreads();

        // ---- resolve exact top-10 (fast path: 10 <= n <= CAND first try) ----
        float thF = THRESH0;
        unsigned long long thK = 0ULL;
        bool useKey = false;
        int iter = 0;
        for (;;) {
            const int n = s_cnt;
            const bool done = (n >= 10 && n <= CAND) || iter >= 32;
            if (done || n > CAND) {
                if (warp == 0) {
                    const int mq = min(n, CAND);
                    for (int kk = 0; kk < 10; ++kk) {
                        unsigned long long v = 0ULL;
                        for (int i = lane; i < mq; i += 32) {
                            unsigned long long b = s_buf[i];
                            if (b > v) v = b;
                        }
#pragma unroll
                        for (int off = 16; off; off >>= 1) {
                            unsigned long long o = __shfl_down_sync(FULLM, v, off);
                            if (o > v) v = o;
                        }
                        unsigned long long w = __shfl_sync(FULLM, v, 0);
                        if (lane == 0) s_top[kk] = w;
                        for (int i = lane; i < mq; i += 32)
                            if (s_buf[i] == w) s_buf[i] = 0ULL;
                    }
                }
                __syncthreads();
                if (done) break;
                thK = s_top[9];
                useKey = true;        // recollect with key >= thK (>=10 guaranteed)
            } else {
                thF -= 4.0f;          // too few: lower the float threshold
                useKey = false;
            }
            __syncthreads();
            if (tid == 0) s_cnt = 0;
            __syncthreads();
            for (int c = tid; c < C; c += 256) {
                const float xv = xr[c];
                if (useKey) {
                    unsigned long long key = makekey(sortkey32(xv), c);
                    if (key >= thK) {
                        int q = atomicAdd(&s_cnt, 1);
                        if (q < CAND) s_buf[q] = key;
                    }
                } else if (xv > thF) {
                    int q = atomicAdd(&s_cnt, 1);
                    if (q < CAND) s_buf[q] = makekey(sortkey32(xv), c);
                }
            }
            __syncthreads();
            ++iter;
        }

        // ---- correction for the top-10 elements (exact math) ----
        const int fl = g_flagrow[row];
        const bool p1 = (fl & 1) != 0, p2 = (fl & 2) != 0, p3 = (fl & 4) != 0;
        const bool has4 = !(p1 | p2 | p3);

        float delta = 0.0f;
        if (tid < 10 && s_top[tid] != 0ULL) {
            const unsigned idx = 0xFFFFFFFFu - (unsigned)(s_top[tid] & 0xFFFFFFFFull);
            const float xv = xr[idx];
            const float yv = yr[idx];
            const float sp = __fdividef(1.0f, 1.0f + __expf(-xv));
            const float sn = fminf(1.05f - sp, 1.0f);
            const bool  pos = (yv != 0.0f);
            const float pv  = pos ? sp : sn;
            const float l   = __logf(fmaxf(pv, 1e-8f));
            const float om  = 1.0f - pv;
            const float om2 = om * om;
            const float w   = pos ? om : om2 * om2;

            const int  cv  = cat[idx];
            const bool inm = inmap[idx] != 0;
            const bool condA = (!inm) && has4;
            const bool condB = (cv == 1 && p1) || (cv == 2 && p2) ||
                               (cv == 3 && p3) || (cv == 4 && has4);
            if (condA || condB) {
                const float factor = (pos ? sn : sp) * 2.0f;   // ALPHA3 = 2
                delta = l * w * (factor - 1.0f);
            }
        }
        if (warp == 0) {
#pragma unroll
            for (int off = 16; off; off >>= 1)
                delta += __shfl_down_sync(FULLM, delta, off);
        }
        if (tid == 0) {
            float tot = delta;
#pragma unroll
            for (int i = 0; i < 8; ++i) tot += s_sumw[i];
            g_rowsum[row] = tot;
        }
        __syncthreads();   // protect s_buf/s_cnt/s_top before next row resets
    }

    // ---- last-block finalize: deterministic double reduction ----
    __threadfence();
    if (tid == 0) s_last = (atomicAdd(&g_count, 1) == gridDim.x - 1) ? 1 : 0;
    __syncthreads();
    if (s_last) {
        __threadfence();
        double* sd = (double*)s_buf;
        double acc = 0.0;
        for (int i = tid; i < B; i += 256) acc += (double)g_rowsum[i];
        sd[tid] = acc;
        __syncthreads();
#pragma unroll
        for (int off = 128; off; off >>= 1) {
            if (tid < off) sd[tid] += sd[tid + off];
            __syncthreads();
        }
        if (tid == 0) { out[0] = -(float)sd[0]; g_count = 0; }
    }
}

extern "C" void kernel_launch(void* const* d_in, const int* in_sizes, int n_in,
                              void* d_out, int out_size)
{
    const float*         X   = (const float*)d_in[0];
    const float*         Y   = (const float*)d_in[1];
    const int*           cat = (const int*)d_in[2];
    const unsigned char* inm = (const unsigned char*)d_in[3];

    const int C = in_sizes[2];        // per-class arrays -> 9605
    const int B = in_sizes[0] / C;    // 2048

    int grid = (B + 1) / 2;
    if (grid < 1) grid = 1;

    asl_build<<<(2 * TBL + C + 255) / 256, 256>>>(cat, C);
    asl_ykernel<<<B, 256>>>(Y, C);
    asl_row_kernel<<<grid, 256>>>(X, Y, cat, inm, C, B, (float*)d_out);
}

// round 15
// speedup vs baseline: 1.3366x; 1.3366x over previous
#include <cuda_runtime.h>
#include <cstdint>

#define CAND 512           // candidate buffer entries (u64)
#define TBL  1024          // bins per table
#define XSCALE 51.2f       // TBL / 20  (range [-10, 10])
#define XOFF   512.0f      // 10 * XSCALE
#define THRESH0 2.7f       // prefilter threshold (fallback makes any value correct)
#define FULLM 0xFFFFFFFFu

static __device__ float g_rowsum[8192];
static __device__ float g_table[2 * TBL];          // [0..TBL)=f_neg, [TBL..2TBL)=f_pos
static __device__ unsigned char g_catbit[16384];   // (1<<(cat-1))&7
static __device__ int   g_count = 0;

// ---------------------------------------------------------------------------
__device__ __forceinline__ unsigned sortkey32(float x) {
    unsigned u = __float_as_uint(x);
    return u ^ ((unsigned)(((int)u) >> 31) | 0x80000000u);
}
__device__ __forceinline__ unsigned long long makekey(unsigned k32, int c) {
    return ((unsigned long long)k32 << 32) |
           (unsigned long long)(0xFFFFFFFFu - (unsigned)c);
}
// saturating index: negatives clamp to 0 in the F2I itself
__device__ __forceinline__ int tbl_idx(float xv) {
    unsigned j = __float2uint_rz(fmaf(xv, XSCALE, XOFF));
    return (int)umin(j, (unsigned)(TBL - 1));
}

// ---------------------------------------------------------------------------
// Kernel 0: build loss tables (exact math) + catbit LUT.
// ---------------------------------------------------------------------------
__global__ void asl_build(const int* __restrict__ cat, int C)
{
    int j = blockIdx.x * 256 + threadIdx.x;
    if (j < 2 * TBL) {
        bool pos = j >= TBL;
        int  q   = pos ? j - TBL : j;
        float x  = (q + 0.5f) * (20.0f / TBL) - 10.0f;
        float sp = 1.0f / (1.0f + expf(-x));
        float v;
        if (pos) {
            v = logf(fmaxf(sp, 1e-8f)) * (1.0f - sp);
        } else {
            float pv = fminf(1.05f - sp, 1.0f);
            float om = 1.0f - pv;
            float om2 = om * om;
            v = logf(fmaxf(pv, 1e-8f)) * om2 * om2;
        }
        g_table[j] = v;
    }
    int c = j - 2 * TBL;
    if (c >= 0 && c < C)
        g_catbit[c] = (unsigned char)((1 << (cat[c] - 1)) & 7);
}

// ---------------------------------------------------------------------------
// Kernel 1: 2 rows per block; branch-free positive select in the hot loop.
// ---------------------------------------------------------------------------
__global__ void __launch_bounds__(256, 8)
asl_row_kernel(const float* __restrict__ X,
               const float* __restrict__ Y,
               const int*   __restrict__ cat,
               const unsigned char* __restrict__ inmap,
               int C, int B, float* __restrict__ out)
{
    const int tid  = threadIdx.x;
    const int lane = tid & 31;
    const int warp = tid >> 5;

    __shared__ float s_tbl[2 * TBL];              // 8 KB
    __shared__ unsigned long long s_buf[CAND];    // 4 KB
    __shared__ unsigned long long s_top[10];
    __shared__ float s_sumw[8];
    __shared__ int s_flags, s_cnt, s_last;

    {   // table L2 -> smem (once per block, amortized over 2 rows)
        const float4* gt = (const float4*)g_table;
        float4* st = (float4*)s_tbl;
#pragma unroll
        for (int i = tid; i < (2 * TBL) / 4; i += 256) st[i] = gt[i];
    }
    __syncthreads();

    for (int row = blockIdx.x; row < B; row += gridDim.x) {
        if (tid == 0) { s_flags = 0; s_cnt = 0; }
        __syncthreads();

        const float* __restrict__ xr = X + (size_t)row * C;
        const float* __restrict__ yr = Y + (size_t)row * C;

        float sum0 = 0.0f, sum1 = 0.0f;
        int flags = 0;

        // alignment: first element index whose address is 16B aligned
        const int p = (int)((4 - (((size_t)row * (size_t)C) & 3)) & 3);
        const int nv = (C - p) >> 2;
        const int t0 = p + (nv << 2);

        // prologue + tail (<=3 elements each), branch-free select
        for (int c = tid; c < p; c += 256) {
            const float xv = xr[c], yv = yr[c];
            int j = tbl_idx(xv);
            if (yv != 0.0f) { j += TBL; flags |= g_catbit[c]; }
            sum0 += s_tbl[j];
            if (xv > THRESH0) {
                int q = atomicAdd(&s_cnt, 1);
                if (q < CAND) s_buf[q] = makekey(sortkey32(xv), c);
            }
        }
        for (int c = t0 + tid; c < C; c += 256) {
            const float xv = xr[c], yv = yr[c];
            int j = tbl_idx(xv);
            if (yv != 0.0f) { j += TBL; flags |= g_catbit[c]; }
            sum0 += s_tbl[j];
            if (xv > THRESH0) {
                int q = atomicAdd(&s_cnt, 1);
                if (q < CAND) s_buf[q] = makekey(sortkey32(xv), c);
            }
        }

        // ---- main vectorized streaming loop ----
        const float4* __restrict__ x4 = (const float4*)(xr + p);
        const float4* __restrict__ y4 = (const float4*)(yr + p);

        for (int v = tid; v < nv; v += 256) {
            const float4 xq = __ldcs(x4 + v);
            const float4 yq = __ldcs(y4 + v);

            // branch-free: positive elements read the pos half of the table
            int j0 = tbl_idx(xq.x); if (yq.x != 0.0f) j0 += TBL;
            int j1 = tbl_idx(xq.y); if (yq.y != 0.0f) j1 += TBL;
            int j2 = tbl_idx(xq.z); if (yq.z != 0.0f) j2 += TBL;
            int j3 = tbl_idx(xq.w); if (yq.w != 0.0f) j3 += TBL;
            sum0 += s_tbl[j0];
            sum1 += s_tbl[j1];
            sum0 += s_tbl[j2];
            sum1 += s_tbl[j3];

            // flags: small predicated body (y in {0,1})
            const unsigned yb = __float_as_uint(yq.x) | __float_as_uint(yq.y) |
                                __float_as_uint(yq.z) | __float_as_uint(yq.w);
            if (yb != 0u) {
                const int c0 = p + (v << 2);
                if (yq.x != 0.0f) flags |= g_catbit[c0 + 0];
                if (yq.y != 0.0f) flags |= g_catbit[c0 + 1];
                if (yq.z != 0.0f) flags |= g_catbit[c0 + 2];
                if (yq.w != 0.0f) flags |= g_catbit[c0 + 3];
            }

            // collect gate (fires ~36% of warp-iterations)
            const float xm = fmaxf(fmaxf(xq.x, xq.y), fmaxf(xq.z, xq.w));
            if (xm > THRESH0) {
                const int c0 = p + (v << 2);
                if (xq.x > THRESH0) { int q = atomicAdd(&s_cnt, 1); if (q < CAND) s_buf[q] = makekey(sortkey32(xq.x), c0 + 0); }
                if (xq.y > THRESH0) { int q = atomicAdd(&s_cnt, 1); if (q < CAND) s_buf[q] = makekey(sortkey32(xq.y), c0 + 1); }
                if (xq.z > THRESH0) { int q = atomicAdd(&s_cnt, 1); if (q < CAND) s_buf[q] = makekey(sortkey32(xq.z), c0 + 2); }
                if (xq.w > THRESH0) { int q = atomicAdd(&s_cnt, 1); if (q < CAND) s_buf[q] = makekey(sortkey32(xq.w), c0 + 3); }
            }
        }

        // ---- reduce sum & flags ----
        float sum = sum0 + sum1;
#pragma unroll
        for (int off = 16; off; off >>= 1) {
            sum   += __shfl_down_sync(FULLM, sum, off);
            flags |= __shfl_down_sync(FULLM, flags, off);
        }
        if (lane == 0) { s_sumw[warp] = sum; atomicOr(&s_flags, flags); }
        __syncthreads();

        // ---- resolve exact top-10 (fast path: 10 <= n <= CAND first try) ----
        float thF = THRESH0;
        unsigned long long thK = 0ULL;
        bool useKey = false;
        int iter = 0;
        for (;;) {
            const int n = s_cnt;
            const bool done = (n >= 10 && n <= CAND) || iter >= 32;
            if (done || n > CAND) {
                if (warp == 0) {
                    const int m = min(n, CAND);
                    for (int kk = 0; kk < 10; ++kk) {
                        unsigned long long v = 0ULL;
                        for (int i = lane; i < m; i += 32) {
                            unsigned long long b = s_buf[i];
                            if (b > v) v = b;
                        }
#pragma unroll
                        for (int off = 16; off; off >>= 1) {
                            unsigned long long o = __shfl_down_sync(FULLM, v, off);
                            if (o > v) v = o;
                        }
                        unsigned long long w = __shfl_sync(FULLM, v, 0);
                        if (lane == 0) s_top[kk] = w;
                        for (int i = lane; i < m; i += 32)
                            if (s_buf[i] == w) s_buf[i] = 0ULL;
                    }
                }
                __syncthreads();
                if (done) break;
                thK = s_top[9];
                useKey = true;        // recollect with key >= thK (>=10 guaranteed)
            } else {
                thF -= 4.0f;          // too few: lower the float threshold
                useKey = false;
            }
            __syncthreads();
            if (tid == 0) s_cnt = 0;
            __syncthreads();
            for (int c = tid; c < C; c += 256) {
                const float xv = xr[c];
                if (useKey) {
                    unsigned long long key = makekey(sortkey32(xv), c);
                    if (key >= thK) {
                        int q = atomicAdd(&s_cnt, 1);
                        if (q < CAND) s_buf[q] = key;
                    }
                } else if (xv > thF) {
                    int q = atomicAdd(&s_cnt, 1);
                    if (q < CAND) s_buf[q] = makekey(sortkey32(xv), c);
                }
            }
            __syncthreads();
            ++iter;
        }

        // ---- correction for the top-10 elements (exact math) ----
        const int fl = s_flags;
        const bool p1 = (fl & 1) != 0, p2 = (fl & 2) != 0, p3 = (fl & 4) != 0;
        const bool has4 = !(p1 | p2 | p3);

        float delta = 0.0f;
        if (tid < 10 && s_top[tid] != 0ULL) {
            const unsigned idx = 0xFFFFFFFFu - (unsigned)(s_top[tid] & 0xFFFFFFFFull);
            const float xv = xr[idx];
            const float yv = yr[idx];
            const float sp = __fdividef(1.0f, 1.0f + __expf(-xv));
            const float sn = fminf(1.05f - sp, 1.0f);
            const bool  pos = (yv != 0.0f);
            const float pv  = pos ? sp : sn;
            const float l   = __logf(fmaxf(pv, 1e-8f));
            const float om  = 1.0f - pv;
            const float om2 = om * om;
            const float w   = pos ? om : om2 * om2;

            const int  cv  = cat[idx];
            const bool inm = inmap[idx] != 0;
            const bool condA = (!inm) && has4;
            const bool condB = (cv == 1 && p1) || (cv == 2 && p2) ||
                               (cv == 3 && p3) || (cv == 4 && has4);
            if (condA || condB) {
                const float factor = (pos ? sn : sp) * 2.0f;   // ALPHA3 = 2
                delta = l * w * (factor - 1.0f);
            }
        }
        if (warp == 0) {
#pragma unroll
            for (int off = 16; off; off >>= 1)
                delta += __shfl_down_sync(FULLM, delta, off);
        }
        if (tid == 0) {
            float tot = delta;
#pragma unroll
            for (int i = 0; i < 8; ++i) tot += s_sumw[i];
            g_rowsum[row] = tot;
        }
        __syncthreads();   // protect s_buf/s_cnt/s_top before next row resets
    }

    // ---- last-block finalize: deterministic double reduction ----
    __threadfence();
    if (tid == 0) s_last = (atomicAdd(&g_count, 1) == gridDim.x - 1) ? 1 : 0;
    __syncthreads();
    if (s_last) {
        __threadfence();
        double* sd = (double*)s_buf;
        double acc = 0.0;
        for (int i = tid; i < B; i += 256) acc += (double)g_rowsum[i];
        sd[tid] = acc;
        __syncthreads();
#pragma unroll
        for (int off = 128; off; off >>= 1) {
            if (tid < off) sd[tid] += sd[tid + off];
            __syncthreads();
        }
        if (tid == 0) { out[0] = -(float)sd[0]; g_count = 0; }
    }
}

extern "C" void kernel_launch(void* const* d_in, const int* in_sizes, int n_in,
                              void* d_out, int out_size)
{
    const float*         X   = (const float*)d_in[0];
    const float*         Y   = (const float*)d_in[1];
    const int*           cat = (const int*)d_in[2];
    const unsigned char* inm = (const unsigned char*)d_in[3];

    const int C = in_sizes[2];        // per-class arrays -> 9605
    const int B = in_sizes[0] / C;    // 2048

    int grid = (B + 1) / 2;           // 2 rows per block, single resident wave
    if (grid < 1) grid = 1;

    asl_build<<<(2 * TBL + C + 255) / 256, 256>>>(cat, C);
    asl_row_kernel<<<grid, 256>>>(X, Y, cat, inm, C, B, (float*)d_out);
}

// round 16
// speedup vs baseline: 1.4013x; 1.0484x over previous
#include <cuda_runtime.h>
#include <cstdint>

#define CAND 512           // candidate buffer entries (u64)
#define TBL  1024          // bins per table
#define XSCALE 51.2f       // TBL / 20  (range [-10, 10])
#define XOFF   512.0f      // 10 * XSCALE
#define THRESH0 2.7f       // prefilter threshold (fallback makes any value correct)
#define FULLM 0xFFFFFFFFu

static __device__ float g_rowsum[8192];
static __device__ float g_table[2 * TBL];          // [0..TBL)=f_neg, [TBL..2TBL)=f_pos
static __device__ unsigned char g_catbit[16384];   // (1<<(cat-1))&7
static __device__ int   g_clist[16384];            // (c<<3)|catbit for catbit!=0
static __device__ int   g_ncl = 0;                 // list length (reset each launch)
static __device__ int   g_count = 0;

// ---------------------------------------------------------------------------
__device__ __forceinline__ unsigned sortkey32(float x) {
    unsigned u = __float_as_uint(x);
    return u ^ ((unsigned)(((int)u) >> 31) | 0x80000000u);
}
__device__ __forceinline__ unsigned long long makekey(unsigned k32, int c) {
    return ((unsigned long long)k32 << 32) |
           (unsigned long long)(0xFFFFFFFFu - (unsigned)c);
}
// saturating index: negatives clamp to 0 in the F2I itself
__device__ __forceinline__ int tbl_idx(float xv) {
    unsigned j = __float2uint_rz(fmaf(xv, XSCALE, XOFF));
    return (int)umin(j, (unsigned)(TBL - 1));
}
// exact select of table half: y in {0.0f, 1.0f}; 0x3F800000>>13 & 0x400 == TBL
__device__ __forceinline__ int pos_off(float yv) {
    return (int)((__float_as_uint(yv) >> 13) & (unsigned)TBL);
}

// ---------------------------------------------------------------------------
// Kernel 0: build loss tables (exact math) + catbit LUT + whitelist class list.
// ---------------------------------------------------------------------------
__global__ void asl_build(const int* __restrict__ cat, int C)
{
    int j = blockIdx.x * 256 + threadIdx.x;
    if (j < 2 * TBL) {
        bool pos = j >= TBL;
        int  q   = pos ? j - TBL : j;
        float x  = (q + 0.5f) * (20.0f / TBL) - 10.0f;
        float sp = 1.0f / (1.0f + expf(-x));
        float v;
        if (pos) {
            v = logf(fmaxf(sp, 1e-8f)) * (1.0f - sp);
        } else {
            float pv = fminf(1.05f - sp, 1.0f);
            float om = 1.0f - pv;
            float om2 = om * om;
            v = logf(fmaxf(pv, 1e-8f)) * om2 * om2;
        }
        g_table[j] = v;
    }
    int c = j - 2 * TBL;
    if (c >= 0 && c < C) {
        unsigned char cb = (unsigned char)((1 << (cat[c] - 1)) & 7);
        g_catbit[c] = cb;
        if (cb) {                       // compact whitelist classes (~1% of C)
            int q = atomicAdd(&g_ncl, 1);
            g_clist[q] = (c << 3) | (int)cb;
        }
    }
}

// ---------------------------------------------------------------------------
// Kernel 1: 2 rows per block; flags via class list; branch-free hot loop.
// ---------------------------------------------------------------------------
__global__ void __launch_bounds__(256, 8)
asl_row_kernel(const float* __restrict__ X,
               const float* __restrict__ Y,
               const int*   __restrict__ cat,
               const unsigned char* __restrict__ inmap,
               int C, int B, float* __restrict__ out)
{
    const int tid  = threadIdx.x;
    const int lane = tid & 31;
    const int warp = tid >> 5;

    __shared__ float s_tbl[2 * TBL];              // 8 KB
    __shared__ unsigned long long s_buf[CAND];    // 4 KB
    __shared__ unsigned long long s_top[10];
    __shared__ float s_sumw[8];
    __shared__ int s_flags, s_cnt, s_last;

    {   // table L2 -> smem (once per block, amortized over 2 rows)
        const float4* gt = (const float4*)g_table;
        float4* st = (float4*)s_tbl;
#pragma unroll
        for (int i = tid; i < (2 * TBL) / 4; i += 256) st[i] = gt[i];
    }
    const int ncl = g_ncl;
    __syncthreads();

    for (int row = blockIdx.x; row < B; row += gridDim.x) {
        if (tid == 0) { s_flags = 0; s_cnt = 0; }
        __syncthreads();

        const float* __restrict__ xr = X + (size_t)row * C;
        const float* __restrict__ yr = Y + (size_t)row * C;

        float sum0 = 0.0f, sum1 = 0.0f;

        // ---- whitelist flags: only classes with catbit != 0 (~1% of C) ----
        {
            int fl = 0;
            for (int i = tid; i < ncl; i += 256) {
                const int e = g_clist[i];
                if (yr[e >> 3] != 0.0f) fl |= (e & 7);
            }
            if (fl) atomicOr(&s_flags, fl);
        }

        // alignment: first element index whose address is 16B aligned
        const int p = (int)((4 - (((size_t)row * (size_t)C) & 3)) & 3);
        const int nv = (C - p) >> 2;
        const int t0 = p + (nv << 2);

        // prologue + tail (<=3 elements each)
        for (int c = tid; c < p; c += 256) {
            const float xv = xr[c];
            sum0 += s_tbl[tbl_idx(xv) + pos_off(yr[c])];
            if (xv > THRESH0) {
                int q = atomicAdd(&s_cnt, 1);
                if (q < CAND) s_buf[q] = makekey(sortkey32(xv), c);
            }
        }
        for (int c = t0 + tid; c < C; c += 256) {
            const float xv = xr[c];
            sum0 += s_tbl[tbl_idx(xv) + pos_off(yr[c])];
            if (xv > THRESH0) {
                int q = atomicAdd(&s_cnt, 1);
                if (q < CAND) s_buf[q] = makekey(sortkey32(xv), c);
            }
        }

        // ---- main vectorized streaming loop (branch-free per element) ----
        const float4* __restrict__ x4 = (const float4*)(xr + p);
        const float4* __restrict__ y4 = (const float4*)(yr + p);

        for (int v = tid; v < nv; v += 256) {
            const float4 xq = __ldcs(x4 + v);
            const float4 yq = __ldcs(y4 + v);

            sum0 += s_tbl[tbl_idx(xq.x) + pos_off(yq.x)];
            sum1 += s_tbl[tbl_idx(xq.y) + pos_off(yq.y)];
            sum0 += s_tbl[tbl_idx(xq.z) + pos_off(yq.z)];
            sum1 += s_tbl[tbl_idx(xq.w) + pos_off(yq.w)];

            // collect gate (fires ~36% of warp-iterations)
            const float xm = fmaxf(fmaxf(xq.x, xq.y), fmaxf(xq.z, xq.w));
            if (xm > THRESH0) {
                const int c0 = p + (v << 2);
                if (xq.x > THRESH0) { int q = atomicAdd(&s_cnt, 1); if (q < CAND) s_buf[q] = makekey(sortkey32(xq.x), c0 + 0); }
                if (xq.y > THRESH0) { int q = atomicAdd(&s_cnt, 1); if (q < CAND) s_buf[q] = makekey(sortkey32(xq.y), c0 + 1); }
                if (xq.z > THRESH0) { int q = atomicAdd(&s_cnt, 1); if (q < CAND) s_buf[q] = makekey(sortkey32(xq.z), c0 + 2); }
                if (xq.w > THRESH0) { int q = atomicAdd(&s_cnt, 1); if (q < CAND) s_buf[q] = makekey(sortkey32(xq.w), c0 + 3); }
            }
        }

        // ---- reduce sum ----
        float sum = sum0 + sum1;
#pragma unroll
        for (int off = 16; off; off >>= 1)
            sum += __shfl_down_sync(FULLM, sum, off);
        if (lane == 0) s_sumw[warp] = sum;
        __syncthreads();

        // ---- resolve exact top-10 (fast path: 10 <= n <= CAND first try) ----
        float thF = THRESH0;
        unsigned long long thK = 0ULL;
        bool useKey = false;
        int iter = 0;
        for (;;) {
            const int n = s_cnt;
            const bool done = (n >= 10 && n <= CAND) || iter >= 32;
            if (done || n > CAND) {
                if (warp == 0) {
                    const int m = min(n, CAND);
                    for (int kk = 0; kk < 10; ++kk) {
                        unsigned long long v = 0ULL;
                        for (int i = lane; i < m; i += 32) {
                            unsigned long long b = s_buf[i];
                            if (b > v) v = b;
                        }
#pragma unroll
                        for (int off = 16; off; off >>= 1) {
                            unsigned long long o = __shfl_down_sync(FULLM, v, off);
                            if (o > v) v = o;
                        }
                        unsigned long long w = __shfl_sync(FULLM, v, 0);
                        if (lane == 0) s_top[kk] = w;
                        for (int i = lane; i < m; i += 32)
                            if (s_buf[i] == w) s_buf[i] = 0ULL;
                    }
                }
                __syncthreads();
                if (done) break;
                thK = s_top[9];
                useKey = true;        // recollect with key >= thK (>=10 guaranteed)
            } else {
                thF -= 4.0f;          // too few: lower the float threshold
                useKey = false;
            }
            __syncthreads();
            if (tid == 0) s_cnt = 0;
            __syncthreads();
            for (int c = tid; c < C; c += 256) {
                const float xv = xr[c];
                if (useKey) {
                    unsigned long long key = makekey(sortkey32(xv), c);
                    if (key >= thK) {
                        int q = atomicAdd(&s_cnt, 1);
                        if (q < CAND) s_buf[q] = key;
                    }
                } else if (xv > thF) {
                    int q = atomicAdd(&s_cnt, 1);
                    if (q < CAND) s_buf[q] = makekey(sortkey32(xv), c);
                }
            }
            __syncthreads();
            ++iter;
        }

        // ---- correction for the top-10 elements (exact math) ----
        const int fl = s_flags;
        const bool p1 = (fl & 1) != 0, p2 = (fl & 2) != 0, p3 = (fl & 4) != 0;
        const bool has4 = !(p1 | p2 | p3);

        float delta = 0.0f;
        if (tid < 10 && s_top[tid] != 0ULL) {
            const unsigned idx = 0xFFFFFFFFu - (unsigned)(s_top[tid] & 0xFFFFFFFFull);
            const float xv = xr[idx];
            const float yv = yr[idx];
            const float sp = __fdividef(1.0f, 1.0f + __expf(-xv));
            const float sn = fminf(1.05f - sp, 1.0f);
            const bool  pos = (yv != 0.0f);
            const float pv  = pos ? sp : sn;
            const float l   = __logf(fmaxf(pv, 1e-8f));
            const float om  = 1.0f - pv;
            const float om2 = om * om;
            const float w   = pos ? om : om2 * om2;

            const int  cv  = cat[idx];
            const bool inm = inmap[idx] != 0;
            const bool condA = (!inm) && has4;
            const bool condB = (cv == 1 && p1) || (cv == 2 && p2) ||
                               (cv == 3 && p3) || (cv == 4 && has4);
            if (condA || condB) {
                const float factor = (pos ? sn : sp) * 2.0f;   // ALPHA3 = 2
                delta = l * w * (factor - 1.0f);
            }
        }
        if (warp == 0) {
#pragma unroll
            for (int off = 16; off; off >>= 1)
                delta += __shfl_down_sync(FULLM, delta, off);
        }
        if (tid == 0) {
            float tot = delta;
#pragma unroll
            for (int i = 0; i < 8; ++i) tot += s_sumw[i];
            g_rowsum[row] = tot;
        }
        __syncthreads();   // protect s_buf/s_cnt/s_top before next row resets
    }

    // ---- last-block finalize: deterministic double reduction + resets ----
    __threadfence();
    if (tid == 0) s_last = (atomicAdd(&g_count, 1) == gridDim.x - 1) ? 1 : 0;
    __syncthreads();
    if (s_last) {
        __threadfence();
        double* sd = (double*)s_buf;
        double acc = 0.0;
        for (int i = tid; i < B; i += 256) acc += (double)g_rowsum[i];
        sd[tid] = acc;
        __syncthreads();
#pragma unroll
        for (int off = 128; off; off >>= 1) {
            if (tid < off) sd[tid] += sd[tid + off];
            __syncthreads();
        }
        if (tid == 0) {
            out[0] = -(float)sd[0];
            g_count = 0;
            g_ncl = 0;     // next launch's build kernel re-compacts from 0
        }
    }
}

extern "C" void kernel_launch(void* const* d_in, const int* in_sizes, int n_in,
                              void* d_out, int out_size)
{
    const float*         X   = (const float*)d_in[0];
    const float*         Y   = (const float*)d_in[1];
    const int*           cat = (const int*)d_in[2];
    const unsigned char* inm = (const unsigned char*)d_in[3];

    const int C = in_sizes[2];        // per-class arrays -> 9605
    const int B = in_sizes[0] / C;    // 2048

    int grid = (B + 1) / 2;           // 2 rows per block, single resident wave
    if (grid < 1) grid = 1;

    asl_build<<<(2 * TBL + C + 255) / 256, 256>>>(cat, C);
    asl_row_kernel<<<grid, 256>>>(X, Y, cat, inm, C, B, (float*)d_out);
}